// round 16
// baseline (speedup 1.0000x reference)
#include <cuda_runtime.h>

// S4D via Vandermonde factorization as per-h GEMMs on tensor cores:
//   l = 64q + r;  out[h, 64q+r] = sum_k A[q,k]*B[k,r],  k = 2n+{0,1}:
//     A[q,2n] = Re(u W^q), A[q,2n+1] = -Im(u W^q)   (W = w^64)
//     B[2n,r] = Re(w^r),   B[2n+1,r] =  Im(w^r)
// mma.sync.m16n8k16 bf16, 3-product split, hi/lo interleaved as uint2.
// TWO h per block (grid 512), three 16KB swizzled smem regions (48KB total):
//   genA0,genB0 | genB1 + MMA(h0) overlapped | genA1 | MMA(h1)
// XOR swizzle (j ^ (row&7)<<2) replaces padding: conflict-free for all
// access patterns. Params computed per-thread (no setup warp, fewer barriers).
// 4 blocks/SM (reg cap 64) -> 512 blocks = 0.86 waves: single wave.

#define HH      1024
#define NH      32
#define LL      4096
#define THREADS 256

#define TWO_PI      6.283185307179586f
#define INV_TWO_PI  0.15915494309189535f

#define SWZ(row, j) ((j) ^ (((row) & 7) << 2))

// pack(hi, lo): result.hi16 = bf16_rn(hi), result.lo16 = bf16_rn(lo)
__device__ __forceinline__ unsigned pack_bf16x2(float hi, float lo) {
    unsigned r;
    asm("cvt.rn.bf16x2.f32 %0, %1, %2;" : "=r"(r) : "f"(hi), "f"(lo));
    return r;
}

__device__ __forceinline__ uint2 split_pack(float hi_val, float lo_val) {
    unsigned hp = pack_bf16x2(hi_val, lo_val);
    float rh_lo = __uint_as_float(hp << 16);
    float rh_hi = __uint_as_float(hp & 0xFFFF0000u);
    unsigned lp = pack_bf16x2(hi_val - rh_hi, lo_val - rh_lo);
    return make_uint2(hp, lp);
}

#define MMA_BF16(C, A0, A1, A2, A3, B0, B1)                                  \
    asm("mma.sync.aligned.m16n8k16.row.col.f32.bf16.bf16.f32 "               \
        "{%0,%1,%2,%3}, {%4,%5,%6,%7}, {%8,%9}, {%0,%1,%2,%3};"              \
        : "+f"((C)[0]), "+f"((C)[1]), "+f"((C)[2]), "+f"((C)[3])             \
        : "r"(A0), "r"(A1), "r"(A2), "r"(A3), "r"(B0), "r"(B1))

struct SParams {
    float re, turn, wr, wi, ur, ui, Wr, Wi;
};

__device__ __forceinline__ SParams compute_params(
    int h, int n,
    const float* __restrict__ C_param, const float* __restrict__ log_dt,
    const float* __restrict__ log_A_real, const float* __restrict__ A_imag)
{
    SParams P;
    const int hn = h * NH + n;
    float dt = expf(log_dt[h]);
    float Ar = -expf(log_A_real[hn]);
    float Ai = A_imag[hn];
    P.re = Ar * dt;                              // Re(dtA) (<0)
    float im = Ai * dt;                          // Im(dtA)
    float er = expf(P.re);
    float si, co; sincosf(im, &si, &co);
    P.wr = er * co; P.wi = er * si;              // w = exp(dtA)
    // u = 2*C*(w-1)/A
    float numr = P.wr - 1.0f, numi = P.wi;
    float invd = 1.0f / fmaf(Ar, Ar, Ai * Ai);
    float tr = (numr * Ar + numi * Ai) * invd;
    float ti = (numi * Ar - numr * Ai) * invd;
    float Cr = C_param[2 * hn + 0];
    float Ci = C_param[2 * hn + 1];
    P.ur = 2.0f * (Cr * tr - Ci * ti);
    P.ui = 2.0f * (Cr * ti + Ci * tr);
    P.turn = im * INV_TWO_PI;
    // W = w^64 via turn trick
    float amp64 = expf(64.0f * P.re);
    float t64   = P.turn * 64.0f;
    float f64   = t64 - truncf(t64);
    float s64, c64; __sincosf(f64 * TWO_PI, &s64, &c64);
    P.Wr = amp64 * c64; P.Wi = amp64 * s64;
    return P;
}

// Bt[r][gn] = (hi=Im(w^r) : lo=Re(w^r)) for r = 8gw .. 8gw+7
__device__ __forceinline__ void gen_B(uint2 (*TB)[32], const SParams& P,
                                      int gn, int gw) {
    float r0f  = (float)(8 * gw);
    float amp  = __expf(P.re * r0f);
    float turns = P.turn * r0f;
    float frac  = turns - truncf(turns);
    float si, co; __sincosf(frac * TWO_PI, &si, &co);
    float zr = amp * co, zi = amp * si;
    #pragma unroll
    for (int i = 0; i < 8; i++) {
        TB[8 * gw + i][gn ^ (i << 2)] = split_pack(zi, zr);
        float nzr = zr * P.wr - zi * P.wi;
        float nzi = zr * P.wi + zi * P.wr;
        zr = nzr; zi = nzi;
    }
}

// A[q][gn] = (hi=-Im(uW^q) : lo=Re(uW^q)) for q = 8gw .. 8gw+7
__device__ __forceinline__ void gen_A(uint2 (*TA)[32], const SParams& P,
                                      int gn, int gw) {
    float l0f  = (float)(512 * gw);              // 64 * 8gw
    float amp  = __expf(P.re * l0f);
    float turns = P.turn * l0f;
    float frac  = turns - truncf(turns);
    float si, co; __sincosf(frac * TWO_PI, &si, &co);
    float zr = amp * co, zi = amp * si;          // w^{64*8gw}
    float pr = P.ur * zr - P.ui * zi;
    float pi = P.ur * zi + P.ui * zr;
    #pragma unroll
    for (int i = 0; i < 8; i++) {
        TA[8 * gw + i][gn ^ (i << 2)] = split_pack(-pi, pr);
        float tpr = pr * P.Wr - pi * P.Wi;
        float tpi = pr * P.Wi + pi * P.Wr;
        pr = tpr; pi = tpi;
    }
}

// Tensor-core GEMM + store: warp (mw,nw) owns 16q x 32r of out[h].
__device__ __forceinline__ void mma_store(const uint2 (*TA)[32],
                                          const uint2 (*TB)[32],
                                          float* __restrict__ obase,
                                          int warp, int lane) {
    const int mw = warp & 3;
    const int nw = warp >> 2;
    const int g  = lane >> 2;
    const int t  = lane & 3;
    const int qrow = mw * 16 + g;

    float acc[4][4];
    #pragma unroll
    for (int j = 0; j < 4; j++)
        #pragma unroll
        for (int i = 0; i < 4; i++) acc[j][i] = 0.0f;

    const int sw = g << 2;                // row&7 == g for all rows used
    #pragma unroll 1
    for (int kt = 0; kt < 4; kt++) {
        const int kp = 8 * kt + t;
        uint2 va0 = TA[qrow][kp ^ sw];
        uint2 va1 = TA[qrow + 8][kp ^ sw];
        uint2 va2 = TA[qrow][(kp + 4) ^ sw];
        uint2 va3 = TA[qrow + 8][(kp + 4) ^ sw];

        #pragma unroll
        for (int j = 0; j < 4; j++) {
            const int nrow = (nw * 4 + j) * 8 + g;
            uint2 vb0 = TB[nrow][kp ^ sw];
            uint2 vb1 = TB[nrow][(kp + 4) ^ sw];

            MMA_BF16(acc[j], va0.x, va1.x, va2.x, va3.x, vb0.x, vb1.x);
            MMA_BF16(acc[j], va0.x, va1.x, va2.x, va3.x, vb0.y, vb1.y);
            MMA_BF16(acc[j], va0.y, va1.y, va2.y, va3.y, vb0.x, vb1.x);
        }
    }

    #pragma unroll
    for (int j = 0; j < 4; j++) {
        const int r = (nw * 4 + j) * 8 + 2 * t;
        *reinterpret_cast<float2*>(&obase[qrow * 64 + r]) =
            make_float2(acc[j][0], acc[j][1]);
        *reinterpret_cast<float2*>(&obase[(qrow + 8) * 64 + r]) =
            make_float2(acc[j][2], acc[j][3]);
    }
}

__global__ __launch_bounds__(THREADS, 4)
void s4d_kernel(const float* __restrict__ C_param,     // (H, 32, 2)
                const float* __restrict__ log_dt,      // (H,)
                const float* __restrict__ log_A_real,  // (H, 32)
                const float* __restrict__ A_imag,      // (H, 32)
                float* __restrict__ out)               // (H, L)
{
    __shared__ uint2 T[3][64][32];        // exactly 48 KB

    const int tid  = threadIdx.x;
    const int warp = tid >> 5;
    const int lane = tid & 31;
    const int gn   = tid & 31;            // n index for gen
    const int gw   = tid >> 5;            // 8-row chunk for gen
    const int h0   = blockIdx.x * 2;
    const int h1   = h0 + 1;

    // ---- phase a: generate h0 tiles ----
    {
        SParams P0 = compute_params(h0, gn, C_param, log_dt, log_A_real, A_imag);
        gen_A(T[0], P0, gn, gw);
        gen_B(T[1], P0, gn, gw);
    }
    __syncthreads();

    // ---- phase b: gen B(h1) overlapped with MMA(h0) ----
    SParams P1 = compute_params(h1, gn, C_param, log_dt, log_A_real, A_imag);
    gen_B(T[2], P1, gn, gw);
    mma_store(T[0], T[1], out + (size_t)h0 * LL, warp, lane);
    __syncthreads();

    // ---- phase c: gen A(h1) into T[0] (A0 dead after MMA(h0)) ----
    gen_A(T[0], P1, gn, gw);
    __syncthreads();

    // ---- phase d: MMA(h1) ----
    mma_store(T[0], T[2], out + (size_t)h1 * LL, warp, lane);
}

extern "C" void kernel_launch(void* const* d_in, const int* in_sizes, int n_in,
                              void* d_out, int out_size) {
    const float* C_param    = (const float*)d_in[0];
    const float* log_dt     = (const float*)d_in[1];
    const float* log_A_real = (const float*)d_in[2];
    const float* A_imag     = (const float*)d_in[3];
    float* out = (float*)d_out;

    s4d_kernel<<<HH / 2, THREADS>>>(C_param, log_dt, log_A_real, A_imag, out);
}